// round 1
// baseline (speedup 1.0000x reference)
#include <cuda_runtime.h>
#include <math.h>

#define NT 4096   // tokens (B*S)
#define HD 1024   // hidden
#define ID 4096   // intermediate
#define NE 8      // experts

// ---------------- scratch (static device globals; no allocs) ----------------
__device__ int   g_cnt[NE];
__device__ int   g_tok[NE * NT];        // token id per expert slot
__device__ float g_wgt[NE * NT];        // gate weight per expert slot
__device__ int   g_assign[NT * 2];      // per token: its two assignment slots (e*NT + slot)
__device__ float g_act[(size_t)NE * NT * ID];   // gelu(h) activations, indexed by slot
__device__ float g_y[(size_t)NE * NT * HD];     // expert outputs, indexed by slot

// ---------------- reset ----------------
__global__ void reset_kernel() {
    if (threadIdx.x < NE) g_cnt[threadIdx.x] = 0;
}

// ---------------- router: one warp per token ----------------
__global__ void router_kernel(const float* __restrict__ x,
                              const float* __restrict__ Wg) {
    int warp = (blockIdx.x * blockDim.x + threadIdx.x) >> 5;
    int lane = threadIdx.x & 31;
    if (warp >= NT) return;
    const float* xr = x + (size_t)warp * HD;

    float xv[HD / 32];
#pragma unroll
    for (int j = 0; j < HD / 32; j++) xv[j] = xr[lane + j * 32];

    float logit[NE];
#pragma unroll
    for (int e = 0; e < NE; e++) {
        const float* w = Wg + e * HD;
        float s = 0.f;
#pragma unroll
        for (int j = 0; j < HD / 32; j++) s += xv[j] * w[lane + j * 32];
#pragma unroll
        for (int o = 16; o; o >>= 1) s += __shfl_xor_sync(0xffffffffu, s, o);
        logit[e] = s;
    }

    if (lane == 0) {
        // top-1 (first index wins ties, matching jax top_k)
        int e0 = 0; float l0 = logit[0];
#pragma unroll
        for (int e = 1; e < NE; e++) if (logit[e] > l0) { l0 = logit[e]; e0 = e; }
        // top-2
        int e1 = -1; float l1 = -3.0e38f;
#pragma unroll
        for (int e = 0; e < NE; e++)
            if (e != e0 && logit[e] > l1) { l1 = logit[e]; e1 = e; }
        // normalized top-2 softmax weights: softmax denom cancels
        float w0 = 1.f / (1.f + expf(l1 - l0));
        float w1 = 1.f - w0;

        int s0 = atomicAdd(&g_cnt[e0], 1);
        g_tok[e0 * NT + s0] = warp;
        g_wgt[e0 * NT + s0] = w0;
        g_assign[warp * 2 + 0] = e0 * NT + s0;

        int s1 = atomicAdd(&g_cnt[e1], 1);
        g_tok[e1 * NT + s1] = warp;
        g_wgt[e1 * NT + s1] = w1;
        g_assign[warp * 2 + 1] = e1 * NT + s1;
    }
}

__device__ __forceinline__ float gelu_exact(float v) {
    return 0.5f * v * (1.f + erff(v * 0.70710678118654752f));
}

// ---------------- FFN1: act = gelu(X_gathered @ W1[e]^T + b1[e]) ----------------
// 64x64 tile, BK=16, 256 threads, 4x4 microtile
__global__ void ffn1_kernel(const float* __restrict__ x,
                            const float* __restrict__ W1,
                            const float* __restrict__ b1) {
    int e = blockIdx.z;
    int cnt = g_cnt[e];
    int m0 = blockIdx.x * 64;
    if (m0 >= cnt) return;
    int n0 = blockIdx.y * 64;

    __shared__ float As[16][64];
    __shared__ float Bs[16][64];
    __shared__ int toks[64];

    int tid = threadIdx.x;
    if (tid < 64) {
        int m = m0 + tid;
        toks[tid] = (m < cnt) ? g_tok[e * NT + m] : -1;
    }
    __syncthreads();

    const float* Be = W1 + (size_t)e * ID * HD;
    int lr = tid >> 2;              // 0..63 load row
    int lk = (tid & 3) << 2;        // 0,4,8,12 load k offset
    int tx = tid & 15, ty = tid >> 4;

    int tokr = toks[lr];
    const float* arow = (tokr >= 0) ? (x + (size_t)tokr * HD) : 0;
    const float* brow = Be + (size_t)(n0 + lr) * HD;

    float acc[4][4] = {};
    for (int k0 = 0; k0 < HD; k0 += 16) {
        float4 av = arow ? *(const float4*)(arow + k0 + lk)
                         : make_float4(0.f, 0.f, 0.f, 0.f);
        float4 bv = *(const float4*)(brow + k0 + lk);
        As[lk + 0][lr] = av.x; As[lk + 1][lr] = av.y;
        As[lk + 2][lr] = av.z; As[lk + 3][lr] = av.w;
        Bs[lk + 0][lr] = bv.x; Bs[lk + 1][lr] = bv.y;
        Bs[lk + 2][lr] = bv.z; Bs[lk + 3][lr] = bv.w;
        __syncthreads();
#pragma unroll
        for (int kk = 0; kk < 16; kk++) {
            float4 a = *(const float4*)&As[kk][ty * 4];
            float4 b = *(const float4*)&Bs[kk][tx * 4];
            acc[0][0] += a.x * b.x; acc[0][1] += a.x * b.y; acc[0][2] += a.x * b.z; acc[0][3] += a.x * b.w;
            acc[1][0] += a.y * b.x; acc[1][1] += a.y * b.y; acc[1][2] += a.y * b.z; acc[1][3] += a.y * b.w;
            acc[2][0] += a.z * b.x; acc[2][1] += a.z * b.y; acc[2][2] += a.z * b.z; acc[2][3] += a.z * b.w;
            acc[3][0] += a.w * b.x; acc[3][1] += a.w * b.y; acc[3][2] += a.w * b.z; acc[3][3] += a.w * b.w;
        }
        __syncthreads();
    }

#pragma unroll
    for (int i = 0; i < 4; i++) {
        int m = m0 + ty * 4 + i;
        if (m >= cnt) continue;
        float* orow = g_act + ((size_t)e * NT + m) * ID;
#pragma unroll
        for (int j = 0; j < 4; j++) {
            int n = n0 + tx * 4 + j;
            orow[n] = gelu_exact(acc[i][j] + b1[e * ID + n]);
        }
    }
}

// ---------------- FFN2: y = act @ W2[e]^T + b2[e] ----------------
__global__ void ffn2_kernel(const float* __restrict__ W2,
                            const float* __restrict__ b2) {
    int e = blockIdx.z;
    int cnt = g_cnt[e];
    int m0 = blockIdx.x * 64;
    if (m0 >= cnt) return;
    int n0 = blockIdx.y * 64;

    __shared__ float As[16][64];
    __shared__ float Bs[16][64];

    int tid = threadIdx.x;
    const float* Ae = g_act + (size_t)e * NT * ID;
    const float* Be = W2 + (size_t)e * HD * ID;
    int lr = tid >> 2;
    int lk = (tid & 3) << 2;
    int tx = tid & 15, ty = tid >> 4;

    const float* arow = Ae + (size_t)(m0 + lr) * ID;   // in-bounds; rows >= cnt discarded
    const float* brow = Be + (size_t)(n0 + lr) * ID;

    float acc[4][4] = {};
    for (int k0 = 0; k0 < ID; k0 += 16) {
        float4 av = *(const float4*)(arow + k0 + lk);
        float4 bv = *(const float4*)(brow + k0 + lk);
        As[lk + 0][lr] = av.x; As[lk + 1][lr] = av.y;
        As[lk + 2][lr] = av.z; As[lk + 3][lr] = av.w;
        Bs[lk + 0][lr] = bv.x; Bs[lk + 1][lr] = bv.y;
        Bs[lk + 2][lr] = bv.z; Bs[lk + 3][lr] = bv.w;
        __syncthreads();
#pragma unroll
        for (int kk = 0; kk < 16; kk++) {
            float4 a = *(const float4*)&As[kk][ty * 4];
            float4 b = *(const float4*)&Bs[kk][tx * 4];
            acc[0][0] += a.x * b.x; acc[0][1] += a.x * b.y; acc[0][2] += a.x * b.z; acc[0][3] += a.x * b.w;
            acc[1][0] += a.y * b.x; acc[1][1] += a.y * b.y; acc[1][2] += a.y * b.z; acc[1][3] += a.y * b.w;
            acc[2][0] += a.z * b.x; acc[2][1] += a.z * b.y; acc[2][2] += a.z * b.z; acc[2][3] += a.z * b.w;
            acc[3][0] += a.w * b.x; acc[3][1] += a.w * b.y; acc[3][2] += a.w * b.z; acc[3][3] += a.w * b.w;
        }
        __syncthreads();
    }

#pragma unroll
    for (int i = 0; i < 4; i++) {
        int m = m0 + ty * 4 + i;
        if (m >= cnt) continue;
        float* orow = g_y + ((size_t)e * NT + m) * HD;
#pragma unroll
        for (int j = 0; j < 4; j++) {
            int n = n0 + tx * 4 + j;
            orow[n] = acc[i][j] + b2[e * HD + n];
        }
    }
}

// ---------------- combine: out[t] = w0*y[a0] + w1*y[a1] (deterministic) ----------------
__global__ void combine_kernel(float* __restrict__ out) {
    int t = blockIdx.x;
    int a0 = g_assign[t * 2 + 0];
    int a1 = g_assign[t * 2 + 1];
    float w0 = g_wgt[a0];
    float w1 = g_wgt[a1];
    const float4* y0 = (const float4*)(g_y + (size_t)a0 * HD);
    const float4* y1 = (const float4*)(g_y + (size_t)a1 * HD);
    float4* o = (float4*)(out + (size_t)t * HD);
    for (int h = threadIdx.x; h < HD / 4; h += blockDim.x) {
        float4 v0 = y0[h], v1 = y1[h], r;
        r.x = w0 * v0.x + w1 * v1.x;
        r.y = w0 * v0.y + w1 * v1.y;
        r.z = w0 * v0.z + w1 * v1.z;
        r.w = w0 * v0.w + w1 * v1.w;
        o[h] = r;
    }
}

extern "C" void kernel_launch(void* const* d_in, const int* in_sizes, int n_in,
                              void* d_out, int out_size) {
    const float* x  = (const float*)d_in[0];
    const float* Wg = (const float*)d_in[1];
    const float* W1 = (const float*)d_in[2];
    const float* b1 = (const float*)d_in[3];
    const float* W2 = (const float*)d_in[4];
    const float* b2 = (const float*)d_in[5];
    float* out = (float*)d_out;

    reset_kernel<<<1, 32>>>();
    router_kernel<<<NT / 4, 128>>>(x, Wg);
    ffn1_kernel<<<dim3(NT / 64, ID / 64, NE), 256>>>(x, W1, b1);
    ffn2_kernel<<<dim3(NT / 64, HD / 64, NE), 256>>>(W2, b2);
    combine_kernel<<<NT, 256>>>(out);
}

// round 3
// speedup vs baseline: 2.5609x; 2.5609x over previous
#include <cuda_runtime.h>
#include <cuda_bf16.h>
#include <math.h>
#include <stdint.h>

#define NT 4096   // tokens (B*S)
#define HD 1024   // hidden
#define ID 4096   // intermediate
#define NE 8      // experts

#define BM 128
#define BN 128
#define BK 32
#define SA 40                 // SMEM row stride (bf16 elems) -> conflict-free
#define ARR_BYTES 10240       // 128 rows * 80B
#define STAGE_BYTES 40960     // Ah, Al, Bh, Bl
#define NSTAGE 3
#define SMEM_TOTAL (NSTAGE * STAGE_BYTES)

// ---------------- scratch (static device globals; no allocs) ----------------
__device__ int   g_cnt[NE];
__device__ int   g_tok[NE * NT];
__device__ float g_wgt[NE * NT];
__device__ int   g_assign[NT * 2];
__device__ __nv_bfloat16 g_xh[(size_t)NE * NT * HD];
__device__ __nv_bfloat16 g_xl[(size_t)NE * NT * HD];
__device__ __nv_bfloat16 g_w1h[(size_t)NE * ID * HD];
__device__ __nv_bfloat16 g_w1l[(size_t)NE * ID * HD];
__device__ __nv_bfloat16 g_w2h[(size_t)NE * HD * ID];
__device__ __nv_bfloat16 g_w2l[(size_t)NE * HD * ID];
__device__ __nv_bfloat16 g_acth[(size_t)NE * NT * ID];
__device__ __nv_bfloat16 g_actl[(size_t)NE * NT * ID];
__device__ float g_y[(size_t)NE * NT * HD];

// ---------------- helpers ----------------
__device__ __forceinline__ uint32_t smem_to_u32(const void* p) {
    uint32_t a;
    asm("{ .reg .u64 t; cvta.to.shared.u64 t, %1; cvt.u32.u64 %0, t; }" : "=r"(a) : "l"(p));
    return a;
}
__device__ __forceinline__ void cp16(uint32_t dst, const void* src) {
    asm volatile("cp.async.cg.shared.global [%0], [%1], 16;" :: "r"(dst), "l"(src));
}
#define CP_COMMIT() asm volatile("cp.async.commit_group;" ::: "memory")
template <int N>
__device__ __forceinline__ void cp_wait() {
    asm volatile("cp.async.wait_group %0;" :: "n"(N) : "memory");
}

__device__ __forceinline__ void mma16816(float* d, const uint32_t* a, const uint32_t* b) {
    asm volatile(
        "mma.sync.aligned.m16n8k16.row.col.f32.bf16.bf16.f32 "
        "{%0,%1,%2,%3}, {%4,%5,%6,%7}, {%8,%9}, {%0,%1,%2,%3};"
        : "+f"(d[0]), "+f"(d[1]), "+f"(d[2]), "+f"(d[3])
        : "r"(a[0]), "r"(a[1]), "r"(a[2]), "r"(a[3]), "r"(b[0]), "r"(b[1]));
}

__device__ __forceinline__ float gelu_exact(float v) {
    return 0.5f * v * (1.f + erff(v * 0.70710678118654752f));
}

// ---------------- reset ----------------
__global__ void reset_kernel() {
    if (threadIdx.x < NE) g_cnt[threadIdx.x] = 0;
}

// ---------------- router: one warp per token ----------------
__global__ void router_kernel(const float* __restrict__ x,
                              const float* __restrict__ Wg) {
    int warp = (blockIdx.x * blockDim.x + threadIdx.x) >> 5;
    int lane = threadIdx.x & 31;
    if (warp >= NT) return;
    const float* xr = x + (size_t)warp * HD;

    float xv[HD / 32];
#pragma unroll
    for (int j = 0; j < HD / 32; j++) xv[j] = xr[lane + j * 32];

    float logit[NE];
#pragma unroll
    for (int e = 0; e < NE; e++) {
        const float* w = Wg + e * HD;
        float s = 0.f;
#pragma unroll
        for (int j = 0; j < HD / 32; j++) s += xv[j] * w[lane + j * 32];
#pragma unroll
        for (int o = 16; o; o >>= 1) s += __shfl_xor_sync(0xffffffffu, s, o);
        logit[e] = s;
    }

    if (lane == 0) {
        int e0 = 0; float l0 = logit[0];
#pragma unroll
        for (int e = 1; e < NE; e++) if (logit[e] > l0) { l0 = logit[e]; e0 = e; }
        int e1 = -1; float l1 = -3.0e38f;
#pragma unroll
        for (int e = 0; e < NE; e++)
            if (e != e0 && logit[e] > l1) { l1 = logit[e]; e1 = e; }
        float w0 = 1.f / (1.f + expf(l1 - l0));
        float w1 = 1.f - w0;

        int s0 = atomicAdd(&g_cnt[e0], 1);
        g_tok[e0 * NT + s0] = warp;
        g_wgt[e0 * NT + s0] = w0;
        g_assign[warp * 2 + 0] = e0 * NT + s0;

        int s1 = atomicAdd(&g_cnt[e1], 1);
        g_tok[e1 * NT + s1] = warp;
        g_wgt[e1 * NT + s1] = w1;
        g_assign[warp * 2 + 1] = e1 * NT + s1;
    }
}

// ---------------- weight conversion f32 -> bf16 hi/lo ----------------
__global__ void wconv_kernel(const float4* __restrict__ src,
                             __nv_bfloat162* __restrict__ h,
                             __nv_bfloat162* __restrict__ l, size_t n4) {
    size_t i = (size_t)blockIdx.x * blockDim.x + threadIdx.x;
    size_t stride = (size_t)gridDim.x * blockDim.x;
    for (; i < n4; i += stride) {
        float4 v = src[i];
        __nv_bfloat16 hx = __float2bfloat16_rn(v.x);
        __nv_bfloat16 hy = __float2bfloat16_rn(v.y);
        __nv_bfloat16 hz = __float2bfloat16_rn(v.z);
        __nv_bfloat16 hw = __float2bfloat16_rn(v.w);
        h[2 * i + 0] = __nv_bfloat162(hx, hy);
        h[2 * i + 1] = __nv_bfloat162(hz, hw);
        l[2 * i + 0] = __nv_bfloat162(__float2bfloat16_rn(v.x - __bfloat162float(hx)),
                                      __float2bfloat16_rn(v.y - __bfloat162float(hy)));
        l[2 * i + 1] = __nv_bfloat162(__float2bfloat16_rn(v.z - __bfloat162float(hz)),
                                      __float2bfloat16_rn(v.w - __bfloat162float(hw)));
    }
}

// ---------------- gather + convert x into dense per-expert A ----------------
__global__ void gather_kernel(const float* __restrict__ x) {
    int e = blockIdx.y;
    int cnt = g_cnt[e];
    int m0 = blockIdx.x * BM;
    int cnt_pad = (cnt + BM - 1) & ~(BM - 1);
    if (m0 >= cnt_pad) return;

    __shared__ int toks[BM];
    int tid = threadIdx.x;
    if (tid < BM) {
        int m = m0 + tid;
        toks[tid] = (m < cnt) ? g_tok[e * NT + m] : -1;
    }
    __syncthreads();

    for (int j = 0; j < 128; j++) {
        int idx = tid + j * 256;
        int r = idx >> 8;
        int c = idx & 255;
        int tok = toks[r];
        float4 v = (tok >= 0) ? *(const float4*)(x + (size_t)tok * HD + c * 4)
                              : make_float4(0.f, 0.f, 0.f, 0.f);
        size_t o2 = ((size_t)(e * NT + m0 + r) * HD + c * 4) >> 1;
        __nv_bfloat16 hx = __float2bfloat16_rn(v.x);
        __nv_bfloat16 hy = __float2bfloat16_rn(v.y);
        __nv_bfloat16 hz = __float2bfloat16_rn(v.z);
        __nv_bfloat16 hw = __float2bfloat16_rn(v.w);
        ((__nv_bfloat162*)g_xh)[o2 + 0] = __nv_bfloat162(hx, hy);
        ((__nv_bfloat162*)g_xh)[o2 + 1] = __nv_bfloat162(hz, hw);
        ((__nv_bfloat162*)g_xl)[o2 + 0] =
            __nv_bfloat162(__float2bfloat16_rn(v.x - __bfloat162float(hx)),
                           __float2bfloat16_rn(v.y - __bfloat162float(hy)));
        ((__nv_bfloat162*)g_xl)[o2 + 1] =
            __nv_bfloat162(__float2bfloat16_rn(v.z - __bfloat162float(hz)),
                           __float2bfloat16_rn(v.w - __bfloat162float(hw)));
    }
}

// ---------------- stage loader: Ah/Al/Bh/Bl 128x32 each, padded stride ----------------
__device__ __forceinline__ void stage_load(uint32_t sbase,
                                           const __nv_bfloat16* ah, const __nv_bfloat16* al,
                                           const __nv_bfloat16* bh, const __nv_bfloat16* bl,
                                           int k0, int kdim, int tid) {
#pragma unroll
    for (int j = 0; j < 2; j++) {
        int c = tid + j * 256;
        int r = c >> 2, ch = c & 3;
        uint32_t off = (uint32_t)(r * (SA * 2) + ch * 16);
        size_t so = (size_t)r * kdim + k0 + ch * 8;
        cp16(sbase + off, ah + so);
        cp16(sbase + ARR_BYTES + off, al + so);
        cp16(sbase + 2 * ARR_BYTES + off, bh + so);
        cp16(sbase + 3 * ARR_BYTES + off, bl + so);
    }
}

// ---------------- split-precision bf16x3 HMMA GEMM ----------------
template <int KDIM, int BROWS, bool GELU_OUT>
__global__ void __launch_bounds__(256)
moe_mma_kernel(const __nv_bfloat16* __restrict__ Ah, const __nv_bfloat16* __restrict__ Al,
               const __nv_bfloat16* __restrict__ Bh, const __nv_bfloat16* __restrict__ Bl,
               const float* __restrict__ bias) {
    int e = blockIdx.z;
    int cnt = g_cnt[e];
    int m0 = blockIdx.x * BM;
    if (m0 >= cnt) return;
    int n0 = blockIdx.y * BN;

    extern __shared__ char smem[];
    uint32_t sb = smem_to_u32(smem);

    int tid = threadIdx.x;
    int wid = tid >> 5;
    int lane = tid & 31;
    int g = lane >> 2, t = lane & 3;
    int wm = (wid >> 2) * 64;     // warp M offset (2 warps over M)
    int wn = (wid & 3) * 32;      // warp N offset (4 warps over N)

    const __nv_bfloat16* ah = Ah + (size_t)(e * NT + m0) * KDIM;
    const __nv_bfloat16* al = Al + (size_t)(e * NT + m0) * KDIM;
    const __nv_bfloat16* bh = Bh + (size_t)(e * BROWS + n0) * KDIM;
    const __nv_bfloat16* bl = Bl + (size_t)(e * BROWS + n0) * KDIM;

    constexpr int NS = KDIM / BK;

    stage_load(sb, ah, al, bh, bl, 0, KDIM, tid);
    CP_COMMIT();
    stage_load(sb + STAGE_BYTES, ah, al, bh, bl, BK, KDIM, tid);
    CP_COMMIT();

    float acc[4][4][4] = {};

    for (int i = 0; i < NS; i++) {
        if (i < NS - 1) cp_wait<1>(); else cp_wait<0>();
        __syncthreads();
        if (i + 2 < NS) {
            stage_load(sb + (uint32_t)((i + 2) % NSTAGE) * STAGE_BYTES,
                       ah, al, bh, bl, (i + 2) * BK, KDIM, tid);
            CP_COMMIT();
        }

        const char* sA = smem + (size_t)(i % NSTAGE) * STAGE_BYTES;
        const char* sB = sA + 2 * ARR_BYTES;

#pragma unroll
        for (int kk = 0; kk < BK; kk += 16) {
            uint32_t AH[4][4], AL[4][4];
#pragma unroll
            for (int mt = 0; mt < 4; mt++) {
                int r = wm + mt * 16 + g;
                const char* p0 = sA + (r * SA + kk) * 2;
                const char* p1 = sA + ((r + 8) * SA + kk) * 2;
                AH[mt][0] = *(const uint32_t*)(p0 + 4 * t);
                AH[mt][1] = *(const uint32_t*)(p1 + 4 * t);
                AH[mt][2] = *(const uint32_t*)(p0 + 4 * t + 16);
                AH[mt][3] = *(const uint32_t*)(p1 + 4 * t + 16);
                AL[mt][0] = *(const uint32_t*)(p0 + ARR_BYTES + 4 * t);
                AL[mt][1] = *(const uint32_t*)(p1 + ARR_BYTES + 4 * t);
                AL[mt][2] = *(const uint32_t*)(p0 + ARR_BYTES + 4 * t + 16);
                AL[mt][3] = *(const uint32_t*)(p1 + ARR_BYTES + 4 * t + 16);
            }
#pragma unroll
            for (int nt = 0; nt < 4; nt++) {
                int rn = wn + nt * 8 + g;
                const char* q = sB + (rn * SA + kk) * 2;
                uint32_t BH[2], BL[2];
                BH[0] = *(const uint32_t*)(q + 4 * t);
                BH[1] = *(const uint32_t*)(q + 4 * t + 16);
                BL[0] = *(const uint32_t*)(q + ARR_BYTES + 4 * t);
                BL[1] = *(const uint32_t*)(q + ARR_BYTES + 4 * t + 16);
#pragma unroll
                for (int mt = 0; mt < 4; mt++) {
                    mma16816(acc[mt][nt], AH[mt], BH);
                    mma16816(acc[mt][nt], AH[mt], BL);
                    mma16816(acc[mt][nt], AL[mt], BH);
                }
            }
        }
        __syncthreads();
    }

    // ---------------- epilogue: bias (+gelu+split) straight from fragments ----------------
#pragma unroll
    for (int mt = 0; mt < 4; mt++) {
#pragma unroll
        for (int nt = 0; nt < 4; nt++) {
            int r0 = m0 + wm + mt * 16 + g;
            int col = n0 + wn + nt * 8 + 2 * t;
            float2 bb = *(const float2*)&bias[(size_t)e * BROWS + col];
            float* c = acc[mt][nt];
            float v00 = c[0] + bb.x, v01 = c[1] + bb.y;   // row r0
            float v10 = c[2] + bb.x, v11 = c[3] + bb.y;   // row r0+8
            if (GELU_OUT) {
                float g00 = gelu_exact(v00), g01 = gelu_exact(v01);
                float g10 = gelu_exact(v10), g11 = gelu_exact(v11);
                __nv_bfloat16 h00 = __float2bfloat16_rn(g00), h01 = __float2bfloat16_rn(g01);
                __nv_bfloat16 h10 = __float2bfloat16_rn(g10), h11 = __float2bfloat16_rn(g11);
                size_t o0 = ((size_t)e * NT + r0) * ID + col;
                size_t o1 = ((size_t)e * NT + r0 + 8) * ID + col;
                *(__nv_bfloat162*)&g_acth[o0] = __nv_bfloat162(h00, h01);
                *(__nv_bfloat162*)&g_acth[o1] = __nv_bfloat162(h10, h11);
                *(__nv_bfloat162*)&g_actl[o0] =
                    __nv_bfloat162(__float2bfloat16_rn(g00 - __bfloat162float(h00)),
                                   __float2bfloat16_rn(g01 - __bfloat162float(h01)));
                *(__nv_bfloat162*)&g_actl[o1] =
                    __nv_bfloat162(__float2bfloat16_rn(g10 - __bfloat162float(h10)),
                                   __float2bfloat16_rn(g11 - __bfloat162float(h11)));
            } else {
                size_t o0 = ((size_t)e * NT + r0) * HD + col;
                size_t o1 = ((size_t)e * NT + r0 + 8) * HD + col;
                *(float2*)&g_y[o0] = make_float2(v00, v01);
                *(float2*)&g_y[o1] = make_float2(v10, v11);
            }
        }
    }
}

// ---------------- combine ----------------
__global__ void combine_kernel(float* __restrict__ out) {
    int t = blockIdx.x;
    int a0 = g_assign[t * 2 + 0];
    int a1 = g_assign[t * 2 + 1];
    float w0 = g_wgt[a0];
    float w1 = g_wgt[a1];
    const float4* y0 = (const float4*)(g_y + (size_t)a0 * HD);
    const float4* y1 = (const float4*)(g_y + (size_t)a1 * HD);
    float4* o = (float4*)(out + (size_t)t * HD);
    for (int h = threadIdx.x; h < HD / 4; h += blockDim.x) {
        float4 v0 = y0[h], v1 = y1[h], r;
        r.x = w0 * v0.x + w1 * v1.x;
        r.y = w0 * v0.y + w1 * v1.y;
        r.z = w0 * v0.z + w1 * v1.z;
        r.w = w0 * v0.w + w1 * v1.w;
        o[h] = r;
    }
}

extern "C" void kernel_launch(void* const* d_in, const int* in_sizes, int n_in,
                              void* d_out, int out_size) {
    const float* x  = (const float*)d_in[0];
    const float* Wg = (const float*)d_in[1];
    const float* W1 = (const float*)d_in[2];
    const float* b1 = (const float*)d_in[3];
    const float* W2 = (const float*)d_in[4];
    const float* b2 = (const float*)d_in[5];
    float* out = (float*)d_out;

    static int init_done = 0;
    if (!init_done) {
        cudaFuncSetAttribute(moe_mma_kernel<HD, ID, true>,
                             cudaFuncAttributeMaxDynamicSharedMemorySize, SMEM_TOTAL);
        cudaFuncSetAttribute(moe_mma_kernel<ID, HD, false>,
                             cudaFuncAttributeMaxDynamicSharedMemorySize, SMEM_TOTAL);
        init_done = 1;
    }

    __nv_bfloat162 *w1h, *w1l, *w2h, *w2l;
    cudaGetSymbolAddress((void**)&w1h, g_w1h);
    cudaGetSymbolAddress((void**)&w1l, g_w1l);
    cudaGetSymbolAddress((void**)&w2h, g_w2h);
    cudaGetSymbolAddress((void**)&w2l, g_w2l);
    const __nv_bfloat16 *xh, *xl, *ath, *atl;
    cudaGetSymbolAddress((void**)&xh, g_xh);
    cudaGetSymbolAddress((void**)&xl, g_xl);
    cudaGetSymbolAddress((void**)&ath, g_acth);
    cudaGetSymbolAddress((void**)&atl, g_actl);

    reset_kernel<<<1, 32>>>();
    router_kernel<<<NT / 4, 128>>>(x, Wg);
    const size_t n4 = (size_t)NE * ID * HD / 4;
    wconv_kernel<<<4096, 256>>>((const float4*)W1, w1h, w1l, n4);
    wconv_kernel<<<4096, 256>>>((const float4*)W2, w2h, w2l, n4);
    gather_kernel<<<dim3(NT / BM, NE), 256>>>(x);

    moe_mma_kernel<HD, ID, true><<<dim3(NT / BM, ID / BN, NE), 256, SMEM_TOTAL>>>(
        xh, xl, (const __nv_bfloat16*)w1h, (const __nv_bfloat16*)w1l, b1);
    moe_mma_kernel<ID, HD, false><<<dim3(NT / BM, HD / BN, NE), 256, SMEM_TOTAL>>>(
        ath, atl, (const __nv_bfloat16*)w2h, (const __nv_bfloat16*)w2l, b2);

    combine_kernel<<<NT, 256>>>(out);
}

// round 4
// speedup vs baseline: 3.6365x; 1.4200x over previous
#include <cuda_runtime.h>
#include <cuda_fp16.h>
#include <math.h>
#include <stdint.h>

#define NT 4096   // tokens (B*S)
#define HD 1024   // hidden
#define ID 4096   // intermediate
#define NE 8      // experts

#define BM 128
#define BN 128
#define BK 32
#define SA 40                 // SMEM row stride (fp16 elems) -> conflict-free
#define ARR_BYTES 10240       // 128 rows * 80B
#define STAGE_BYTES 30720     // A, Bh, Bl
#define NSTAGE 3
#define SMEM_TOTAL (NSTAGE * STAGE_BYTES)

#define WSCALE 32.0f
#define INV_WSCALE 0.03125f

// ---------------- scratch (static device globals; no allocs) ----------------
__device__ int   g_cnt[NE];
__device__ int   g_tok[NE * NT];
__device__ float g_wgt[NE * NT];
__device__ int   g_assign[NT * 2];
__device__ __half g_x[(size_t)NE * NT * HD];
__device__ __half g_w1h[(size_t)NE * ID * HD];
__device__ __half g_w1l[(size_t)NE * ID * HD];
__device__ __half g_w2h[(size_t)NE * HD * ID];
__device__ __half g_w2l[(size_t)NE * HD * ID];
__device__ __half g_act[(size_t)NE * NT * ID];
__device__ float g_y[(size_t)NE * NT * HD];

// ---------------- helpers ----------------
__device__ __forceinline__ uint32_t smem_to_u32(const void* p) {
    uint32_t a;
    asm("{ .reg .u64 t; cvta.to.shared.u64 t, %1; cvt.u32.u64 %0, t; }" : "=r"(a) : "l"(p));
    return a;
}
__device__ __forceinline__ void cp16(uint32_t dst, const void* src) {
    asm volatile("cp.async.cg.shared.global [%0], [%1], 16;" :: "r"(dst), "l"(src));
}
#define CP_COMMIT() asm volatile("cp.async.commit_group;" ::: "memory")
template <int N>
__device__ __forceinline__ void cp_wait() {
    asm volatile("cp.async.wait_group %0;" :: "n"(N) : "memory");
}

__device__ __forceinline__ void mma16816(float* d, const uint32_t* a, const uint32_t* b) {
    asm volatile(
        "mma.sync.aligned.m16n8k16.row.col.f32.f16.f16.f32 "
        "{%0,%1,%2,%3}, {%4,%5,%6,%7}, {%8,%9}, {%0,%1,%2,%3};"
        : "+f"(d[0]), "+f"(d[1]), "+f"(d[2]), "+f"(d[3])
        : "r"(a[0]), "r"(a[1]), "r"(a[2]), "r"(a[3]), "r"(b[0]), "r"(b[1]));
}

__device__ __forceinline__ float gelu_exact(float v) {
    return 0.5f * v * (1.f + erff(v * 0.70710678118654752f));
}

// ---------------- reset ----------------
__global__ void reset_kernel() {
    if (threadIdx.x < NE) g_cnt[threadIdx.x] = 0;
}

// ---------------- router: one warp per token ----------------
__global__ void router_kernel(const float* __restrict__ x,
                              const float* __restrict__ Wg) {
    int warp = (blockIdx.x * blockDim.x + threadIdx.x) >> 5;
    int lane = threadIdx.x & 31;
    if (warp >= NT) return;
    const float* xr = x + (size_t)warp * HD;

    float xv[HD / 32];
#pragma unroll
    for (int j = 0; j < HD / 32; j++) xv[j] = xr[lane + j * 32];

    float logit[NE];
#pragma unroll
    for (int e = 0; e < NE; e++) {
        const float* w = Wg + e * HD;
        float s = 0.f;
#pragma unroll
        for (int j = 0; j < HD / 32; j++) s += xv[j] * w[lane + j * 32];
#pragma unroll
        for (int o = 16; o; o >>= 1) s += __shfl_xor_sync(0xffffffffu, s, o);
        logit[e] = s;
    }

    if (lane == 0) {
        int e0 = 0; float l0 = logit[0];
#pragma unroll
        for (int e = 1; e < NE; e++) if (logit[e] > l0) { l0 = logit[e]; e0 = e; }
        int e1 = -1; float l1 = -3.0e38f;
#pragma unroll
        for (int e = 0; e < NE; e++)
            if (e != e0 && logit[e] > l1) { l1 = logit[e]; e1 = e; }
        float w0 = 1.f / (1.f + expf(l1 - l0));
        float w1 = 1.f - w0;

        int s0 = atomicAdd(&g_cnt[e0], 1);
        g_tok[e0 * NT + s0] = warp;
        g_wgt[e0 * NT + s0] = w0;
        g_assign[warp * 2 + 0] = e0 * NT + s0;

        int s1 = atomicAdd(&g_cnt[e1], 1);
        g_tok[e1 * NT + s1] = warp;
        g_wgt[e1 * NT + s1] = w1;
        g_assign[warp * 2 + 1] = e1 * NT + s1;
    }
}

// ---------------- weight conversion f32 -> fp16 hi/lo (scaled by WSCALE) ----------------
__global__ void wconv_kernel(const float4* __restrict__ src,
                             __half2* __restrict__ h,
                             __half2* __restrict__ l, size_t n4) {
    size_t i = (size_t)blockIdx.x * blockDim.x + threadIdx.x;
    size_t stride = (size_t)gridDim.x * blockDim.x;
    for (; i < n4; i += stride) {
        float4 v = src[i];
        float sx = v.x * WSCALE, sy = v.y * WSCALE, sz = v.z * WSCALE, sw = v.w * WSCALE;
        __half hx = __float2half_rn(sx);
        __half hy = __float2half_rn(sy);
        __half hz = __float2half_rn(sz);
        __half hw = __float2half_rn(sw);
        h[2 * i + 0] = __half2(hx, hy);
        h[2 * i + 1] = __half2(hz, hw);
        l[2 * i + 0] = __half2(__float2half_rn(sx - __half2float(hx)),
                               __float2half_rn(sy - __half2float(hy)));
        l[2 * i + 1] = __half2(__float2half_rn(sz - __half2float(hz)),
                               __float2half_rn(sw - __half2float(hw)));
    }
}

// ---------------- gather + convert x into dense per-expert A (fp16) ----------------
__global__ void gather_kernel(const float* __restrict__ x) {
    int e = blockIdx.y;
    int cnt = g_cnt[e];
    int m0 = blockIdx.x * BM;
    int cnt_pad = (cnt + BM - 1) & ~(BM - 1);
    if (m0 >= cnt_pad) return;

    __shared__ int toks[BM];
    int tid = threadIdx.x;
    if (tid < BM) {
        int m = m0 + tid;
        toks[tid] = (m < cnt) ? g_tok[e * NT + m] : -1;
    }
    __syncthreads();

    for (int j = 0; j < 128; j++) {
        int idx = tid + j * 256;
        int r = idx >> 8;
        int c = idx & 255;
        int tok = toks[r];
        float4 v = (tok >= 0) ? *(const float4*)(x + (size_t)tok * HD + c * 4)
                              : make_float4(0.f, 0.f, 0.f, 0.f);
        size_t o2 = ((size_t)(e * NT + m0 + r) * HD + c * 4) >> 1;
        ((__half2*)g_x)[o2 + 0] = __half2(__float2half_rn(v.x), __float2half_rn(v.y));
        ((__half2*)g_x)[o2 + 1] = __half2(__float2half_rn(v.z), __float2half_rn(v.w));
    }
}

// ---------------- stage loader: A/Bh/Bl 128x32 each, padded stride ----------------
__device__ __forceinline__ void stage_load(uint32_t sbase,
                                           const __half* a,
                                           const __half* bh, const __half* bl,
                                           int k0, int kdim, int tid) {
#pragma unroll
    for (int j = 0; j < 2; j++) {
        int c = tid + j * 256;
        int r = c >> 2, ch = c & 3;
        uint32_t off = (uint32_t)(r * (SA * 2) + ch * 16);
        size_t so = (size_t)r * kdim + k0 + ch * 8;
        cp16(sbase + off, a + so);
        cp16(sbase + ARR_BYTES + off, bh + so);
        cp16(sbase + 2 * ARR_BYTES + off, bl + so);
    }
}

// ---------------- split-precision fp16x2 (B-split) HMMA GEMM ----------------
template <int KDIM, int BROWS, bool GELU_OUT>
__global__ void __launch_bounds__(256)
moe_mma_kernel(const __half* __restrict__ A,
               const __half* __restrict__ Bh, const __half* __restrict__ Bl,
               const float* __restrict__ bias) {
    int e = blockIdx.z;
    int cnt = g_cnt[e];
    int m0 = blockIdx.x * BM;
    if (m0 >= cnt) return;
    int n0 = blockIdx.y * BN;

    extern __shared__ char smem[];
    uint32_t sb = smem_to_u32(smem);

    int tid = threadIdx.x;
    int wid = tid >> 5;
    int lane = tid & 31;
    int g = lane >> 2, t = lane & 3;
    int wm = (wid >> 2) * 64;     // warp M offset (2 warps over M)
    int wn = (wid & 3) * 32;      // warp N offset (4 warps over N)

    const __half* a  = A  + (size_t)(e * NT + m0) * KDIM;
    const __half* bh = Bh + (size_t)(e * BROWS + n0) * KDIM;
    const __half* bl = Bl + (size_t)(e * BROWS + n0) * KDIM;

    constexpr int NS = KDIM / BK;

    stage_load(sb, a, bh, bl, 0, KDIM, tid);
    CP_COMMIT();
    stage_load(sb + STAGE_BYTES, a, bh, bl, BK, KDIM, tid);
    CP_COMMIT();

    float acc[4][4][4] = {};

    for (int i = 0; i < NS; i++) {
        if (i < NS - 1) cp_wait<1>(); else cp_wait<0>();
        __syncthreads();
        if (i + 2 < NS) {
            stage_load(sb + (uint32_t)((i + 2) % NSTAGE) * STAGE_BYTES,
                       a, bh, bl, (i + 2) * BK, KDIM, tid);
            CP_COMMIT();
        }

        const char* sA = smem + (size_t)(i % NSTAGE) * STAGE_BYTES;
        const char* sB = sA + ARR_BYTES;

#pragma unroll
        for (int kk = 0; kk < BK; kk += 16) {
            uint32_t AH[4][4];
#pragma unroll
            for (int mt = 0; mt < 4; mt++) {
                int r = wm + mt * 16 + g;
                const char* p0 = sA + (r * SA + kk) * 2;
                const char* p1 = sA + ((r + 8) * SA + kk) * 2;
                AH[mt][0] = *(const uint32_t*)(p0 + 4 * t);
                AH[mt][1] = *(const uint32_t*)(p1 + 4 * t);
                AH[mt][2] = *(const uint32_t*)(p0 + 4 * t + 16);
                AH[mt][3] = *(const uint32_t*)(p1 + 4 * t + 16);
            }
#pragma unroll
            for (int nt = 0; nt < 4; nt++) {
                int rn = wn + nt * 8 + g;
                const char* q = sB + (rn * SA + kk) * 2;
                uint32_t BH[2], BL[2];
                BH[0] = *(const uint32_t*)(q + 4 * t);
                BH[1] = *(const uint32_t*)(q + 4 * t + 16);
                BL[0] = *(const uint32_t*)(q + ARR_BYTES + 4 * t);
                BL[1] = *(const uint32_t*)(q + ARR_BYTES + 4 * t + 16);
#pragma unroll
                for (int mt = 0; mt < 4; mt++) {
                    mma16816(acc[mt][nt], AH[mt], BH);
                    mma16816(acc[mt][nt], AH[mt], BL);
                }
            }
        }
        __syncthreads();
    }

    // ---------------- epilogue: unscale + bias (+gelu) straight from fragments ----------------
#pragma unroll
    for (int mt = 0; mt < 4; mt++) {
#pragma unroll
        for (int nt = 0; nt < 4; nt++) {
            int r0 = m0 + wm + mt * 16 + g;
            int col = n0 + wn + nt * 8 + 2 * t;
            float2 bb = *(const float2*)&bias[(size_t)e * BROWS + col];
            float* c = acc[mt][nt];
            float v00 = c[0] * INV_WSCALE + bb.x, v01 = c[1] * INV_WSCALE + bb.y;
            float v10 = c[2] * INV_WSCALE + bb.x, v11 = c[3] * INV_WSCALE + bb.y;
            if (GELU_OUT) {
                float g00 = gelu_exact(v00), g01 = gelu_exact(v01);
                float g10 = gelu_exact(v10), g11 = gelu_exact(v11);
                size_t o0 = ((size_t)e * NT + r0) * ID + col;
                size_t o1 = ((size_t)e * NT + r0 + 8) * ID + col;
                *(__half2*)&g_act[o0] = __half2(__float2half_rn(g00), __float2half_rn(g01));
                *(__half2*)&g_act[o1] = __half2(__float2half_rn(g10), __float2half_rn(g11));
            } else {
                size_t o0 = ((size_t)e * NT + r0) * HD + col;
                size_t o1 = ((size_t)e * NT + r0 + 8) * HD + col;
                *(float2*)&g_y[o0] = make_float2(v00, v01);
                *(float2*)&g_y[o1] = make_float2(v10, v11);
            }
        }
    }
}

// ---------------- combine ----------------
__global__ void combine_kernel(float* __restrict__ out) {
    int t = blockIdx.x;
    int a0 = g_assign[t * 2 + 0];
    int a1 = g_assign[t * 2 + 1];
    float w0 = g_wgt[a0];
    float w1 = g_wgt[a1];
    const float4* y0 = (const float4*)(g_y + (size_t)a0 * HD);
    const float4* y1 = (const float4*)(g_y + (size_t)a1 * HD);
    float4* o = (float4*)(out + (size_t)t * HD);
    for (int h = threadIdx.x; h < HD / 4; h += blockDim.x) {
        float4 v0 = y0[h], v1 = y1[h], r;
        r.x = w0 * v0.x + w1 * v1.x;
        r.y = w0 * v0.y + w1 * v1.y;
        r.z = w0 * v0.z + w1 * v1.z;
        r.w = w0 * v0.w + w1 * v1.w;
        o[h] = r;
    }
}

extern "C" void kernel_launch(void* const* d_in, const int* in_sizes, int n_in,
                              void* d_out, int out_size) {
    const float* x  = (const float*)d_in[0];
    const float* Wg = (const float*)d_in[1];
    const float* W1 = (const float*)d_in[2];
    const float* b1 = (const float*)d_in[3];
    const float* W2 = (const float*)d_in[4];
    const float* b2 = (const float*)d_in[5];
    float* out = (float*)d_out;

    static int init_done = 0;
    if (!init_done) {
        cudaFuncSetAttribute(moe_mma_kernel<HD, ID, true>,
                             cudaFuncAttributeMaxDynamicSharedMemorySize, SMEM_TOTAL);
        cudaFuncSetAttribute(moe_mma_kernel<ID, HD, false>,
                             cudaFuncAttributeMaxDynamicSharedMemorySize, SMEM_TOTAL);
        init_done = 1;
    }

    __half2 *w1h, *w1l, *w2h, *w2l;
    cudaGetSymbolAddress((void**)&w1h, g_w1h);
    cudaGetSymbolAddress((void**)&w1l, g_w1l);
    cudaGetSymbolAddress((void**)&w2h, g_w2h);
    cudaGetSymbolAddress((void**)&w2l, g_w2l);
    const __half *xp, *actp;
    cudaGetSymbolAddress((void**)&xp, g_x);
    cudaGetSymbolAddress((void**)&actp, g_act);

    reset_kernel<<<1, 32>>>();
    router_kernel<<<NT / 4, 128>>>(x, Wg);
    const size_t n4 = (size_t)NE * ID * HD / 4;
    wconv_kernel<<<4096, 256>>>((const float4*)W1, w1h, w1l, n4);
    wconv_kernel<<<4096, 256>>>((const float4*)W2, w2h, w2l, n4);
    gather_kernel<<<dim3(NT / BM, NE), 256>>>(x);

    moe_mma_kernel<HD, ID, true><<<dim3(NT / BM, ID / BN, NE), 256, SMEM_TOTAL>>>(
        xp, (const __half*)w1h, (const __half*)w1l, b1);
    moe_mma_kernel<ID, HD, false><<<dim3(NT / BM, HD / BN, NE), 256, SMEM_TOTAL>>>(
        actp, (const __half*)w2h, (const __half*)w2l, b2);

    combine_kernel<<<NT, 256>>>(out);
}

// round 5
// speedup vs baseline: 5.9138x; 1.6262x over previous
#include <cuda_runtime.h>
#include <cuda_fp16.h>
#include <math.h>
#include <stdint.h>

#define NT 4096   // tokens (B*S)
#define HD 1024   // hidden
#define ID 4096   // intermediate
#define NE 8      // experts

#define BM 128
#define BN 128
#define BK 32
#define SA 40                 // SMEM row stride (fp16 elems) -> conflict-free
#define ARR_BYTES 10240       // 128 rows * 80B
#define STAGE_BYTES 20480     // A, B
#define NSTAGE 3
#define SMEM_TOTAL (NSTAGE * STAGE_BYTES)

// ---------------- scratch (static device globals; no allocs) ----------------
__device__ int   g_cnt[NE];
__device__ int   g_tok[NE * NT];
__device__ float g_wgt[NE * NT];
__device__ int   g_assign[NT * 2];
__device__ __half g_x[(size_t)NE * NT * HD];
__device__ __half g_w1[(size_t)NE * ID * HD];
__device__ __half g_w2[(size_t)NE * HD * ID];
__device__ __half g_act[(size_t)NE * NT * ID];
__device__ float g_y[(size_t)NE * NT * HD];

// ---------------- helpers ----------------
__device__ __forceinline__ uint32_t smem_to_u32(const void* p) {
    uint32_t a;
    asm("{ .reg .u64 t; cvta.to.shared.u64 t, %1; cvt.u32.u64 %0, t; }" : "=r"(a) : "l"(p));
    return a;
}
__device__ __forceinline__ void cp16(uint32_t dst, const void* src) {
    asm volatile("cp.async.cg.shared.global [%0], [%1], 16;" :: "r"(dst), "l"(src));
}
#define CP_COMMIT() asm volatile("cp.async.commit_group;" ::: "memory")
template <int N>
__device__ __forceinline__ void cp_wait() {
    asm volatile("cp.async.wait_group %0;" :: "n"(N) : "memory");
}

__device__ __forceinline__ void mma16816(float* d, const uint32_t* a, const uint32_t* b) {
    asm volatile(
        "mma.sync.aligned.m16n8k16.row.col.f32.f16.f16.f32 "
        "{%0,%1,%2,%3}, {%4,%5,%6,%7}, {%8,%9}, {%0,%1,%2,%3};"
        : "+f"(d[0]), "+f"(d[1]), "+f"(d[2]), "+f"(d[3])
        : "r"(a[0]), "r"(a[1]), "r"(a[2]), "r"(a[3]), "r"(b[0]), "r"(b[1]));
}

__device__ __forceinline__ float gelu_exact(float v) {
    return 0.5f * v * (1.f + erff(v * 0.70710678118654752f));
}

// ---------------- reset ----------------
__global__ void reset_kernel() {
    if (threadIdx.x < NE) g_cnt[threadIdx.x] = 0;
}

// ---------------- router: one warp per token ----------------
__global__ void router_kernel(const float* __restrict__ x,
                              const float* __restrict__ Wg) {
    int warp = (blockIdx.x * blockDim.x + threadIdx.x) >> 5;
    int lane = threadIdx.x & 31;
    if (warp >= NT) return;
    const float* xr = x + (size_t)warp * HD;

    float xv[HD / 32];
#pragma unroll
    for (int j = 0; j < HD / 32; j++) xv[j] = xr[lane + j * 32];

    float logit[NE];
#pragma unroll
    for (int e = 0; e < NE; e++) {
        const float* w = Wg + e * HD;
        float s = 0.f;
#pragma unroll
        for (int j = 0; j < HD / 32; j++) s += xv[j] * w[lane + j * 32];
#pragma unroll
        for (int o = 16; o; o >>= 1) s += __shfl_xor_sync(0xffffffffu, s, o);
        logit[e] = s;
    }

    if (lane == 0) {
        int e0 = 0; float l0 = logit[0];
#pragma unroll
        for (int e = 1; e < NE; e++) if (logit[e] > l0) { l0 = logit[e]; e0 = e; }
        int e1 = -1; float l1 = -3.0e38f;
#pragma unroll
        for (int e = 0; e < NE; e++)
            if (e != e0 && logit[e] > l1) { l1 = logit[e]; e1 = e; }
        float w0 = 1.f / (1.f + expf(l1 - l0));
        float w1 = 1.f - w0;

        int s0 = atomicAdd(&g_cnt[e0], 1);
        g_tok[e0 * NT + s0] = warp;
        g_wgt[e0 * NT + s0] = w0;
        g_assign[warp * 2 + 0] = e0 * NT + s0;

        int s1 = atomicAdd(&g_cnt[e1], 1);
        g_tok[e1 * NT + s1] = warp;
        g_wgt[e1 * NT + s1] = w1;
        g_assign[warp * 2 + 1] = e1 * NT + s1;
    }
}

// ---------------- weight conversion f32 -> fp16 ----------------
__global__ void wconv_kernel(const float4* __restrict__ src,
                             __half2* __restrict__ h, size_t n4) {
    size_t i = (size_t)blockIdx.x * blockDim.x + threadIdx.x;
    size_t stride = (size_t)gridDim.x * blockDim.x;
    for (; i < n4; i += stride) {
        float4 v = src[i];
        h[2 * i + 0] = __half2(__float2half_rn(v.x), __float2half_rn(v.y));
        h[2 * i + 1] = __half2(__float2half_rn(v.z), __float2half_rn(v.w));
    }
}

// ---------------- gather + convert x into dense per-expert A (fp16) ----------------
__global__ void gather_kernel(const float* __restrict__ x) {
    int e = blockIdx.y;
    int cnt = g_cnt[e];
    int m0 = blockIdx.x * BM;
    int cnt_pad = (cnt + BM - 1) & ~(BM - 1);
    if (m0 >= cnt_pad) return;

    __shared__ int toks[BM];
    int tid = threadIdx.x;
    if (tid < BM) {
        int m = m0 + tid;
        toks[tid] = (m < cnt) ? g_tok[e * NT + m] : -1;
    }
    __syncthreads();

    for (int j = 0; j < 128; j++) {
        int idx = tid + j * 256;
        int r = idx >> 8;
        int c = idx & 255;
        int tok = toks[r];
        float4 v = (tok >= 0) ? *(const float4*)(x + (size_t)tok * HD + c * 4)
                              : make_float4(0.f, 0.f, 0.f, 0.f);
        size_t o2 = ((size_t)(e * NT + m0 + r) * HD + c * 4) >> 1;
        ((__half2*)g_x)[o2 + 0] = __half2(__float2half_rn(v.x), __float2half_rn(v.y));
        ((__half2*)g_x)[o2 + 1] = __half2(__float2half_rn(v.z), __float2half_rn(v.w));
    }
}

// ---------------- stage loader: A/B 128x32 each, padded stride ----------------
__device__ __forceinline__ void stage_load(uint32_t sbase,
                                           const __half* a, const __half* b,
                                           int k0, int kdim, int tid) {
#pragma unroll
    for (int j = 0; j < 2; j++) {
        int c = tid + j * 256;
        int r = c >> 2, ch = c & 3;
        uint32_t off = (uint32_t)(r * (SA * 2) + ch * 16);
        size_t so = (size_t)r * kdim + k0 + ch * 8;
        cp16(sbase + off, a + so);
        cp16(sbase + ARR_BYTES + off, b + so);
    }
}

// ---------------- single-pass fp16 HMMA GEMM ----------------
template <int KDIM, int BROWS, bool GELU_OUT>
__global__ void __launch_bounds__(256)
moe_mma_kernel(const __half* __restrict__ A, const __half* __restrict__ B,
               const float* __restrict__ bias) {
    int e = blockIdx.z;
    int cnt = g_cnt[e];
    int m0 = blockIdx.x * BM;
    if (m0 >= cnt) return;
    int n0 = blockIdx.y * BN;

    extern __shared__ char smem[];
    uint32_t sb = smem_to_u32(smem);

    int tid = threadIdx.x;
    int wid = tid >> 5;
    int lane = tid & 31;
    int g = lane >> 2, t = lane & 3;
    int wm = (wid >> 2) * 64;     // warp M offset (2 warps over M)
    int wn = (wid & 3) * 32;      // warp N offset (4 warps over N)

    const __half* a = A + (size_t)(e * NT + m0) * KDIM;
    const __half* b = B + (size_t)(e * BROWS + n0) * KDIM;

    constexpr int NS = KDIM / BK;

    stage_load(sb, a, b, 0, KDIM, tid);
    CP_COMMIT();
    stage_load(sb + STAGE_BYTES, a, b, BK, KDIM, tid);
    CP_COMMIT();

    float acc[4][4][4] = {};

    for (int i = 0; i < NS; i++) {
        if (i < NS - 1) cp_wait<1>(); else cp_wait<0>();
        __syncthreads();
        if (i + 2 < NS) {
            stage_load(sb + (uint32_t)((i + 2) % NSTAGE) * STAGE_BYTES,
                       a, b, (i + 2) * BK, KDIM, tid);
            CP_COMMIT();
        }

        const char* sA = smem + (size_t)(i % NSTAGE) * STAGE_BYTES;
        const char* sB = sA + ARR_BYTES;

#pragma unroll
        for (int kk = 0; kk < BK; kk += 16) {
            uint32_t AH[4][4];
#pragma unroll
            for (int mt = 0; mt < 4; mt++) {
                int r = wm + mt * 16 + g;
                const char* p0 = sA + (r * SA + kk) * 2;
                const char* p1 = sA + ((r + 8) * SA + kk) * 2;
                AH[mt][0] = *(const uint32_t*)(p0 + 4 * t);
                AH[mt][1] = *(const uint32_t*)(p1 + 4 * t);
                AH[mt][2] = *(const uint32_t*)(p0 + 4 * t + 16);
                AH[mt][3] = *(const uint32_t*)(p1 + 4 * t + 16);
            }
#pragma unroll
            for (int nt = 0; nt < 4; nt++) {
                int rn = wn + nt * 8 + g;
                const char* q = sB + (rn * SA + kk) * 2;
                uint32_t BH[2];
                BH[0] = *(const uint32_t*)(q + 4 * t);
                BH[1] = *(const uint32_t*)(q + 4 * t + 16);
#pragma unroll
                for (int mt = 0; mt < 4; mt++) {
                    mma16816(acc[mt][nt], AH[mt], BH);
                }
            }
        }
        __syncthreads();
    }

    // ---------------- epilogue: bias (+gelu) straight from fragments ----------------
#pragma unroll
    for (int mt = 0; mt < 4; mt++) {
#pragma unroll
        for (int nt = 0; nt < 4; nt++) {
            int r0 = m0 + wm + mt * 16 + g;
            int col = n0 + wn + nt * 8 + 2 * t;
            float2 bb = *(const float2*)&bias[(size_t)e * BROWS + col];
            float* c = acc[mt][nt];
            float v00 = c[0] + bb.x, v01 = c[1] + bb.y;
            float v10 = c[2] + bb.x, v11 = c[3] + bb.y;
            if (GELU_OUT) {
                float g00 = gelu_exact(v00), g01 = gelu_exact(v01);
                float g10 = gelu_exact(v10), g11 = gelu_exact(v11);
                size_t o0 = ((size_t)e * NT + r0) * ID + col;
                size_t o1 = ((size_t)e * NT + r0 + 8) * ID + col;
                *(__half2*)&g_act[o0] = __half2(__float2half_rn(g00), __float2half_rn(g01));
                *(__half2*)&g_act[o1] = __half2(__float2half_rn(g10), __float2half_rn(g11));
            } else {
                size_t o0 = ((size_t)e * NT + r0) * HD + col;
                size_t o1 = ((size_t)e * NT + r0 + 8) * HD + col;
                *(float2*)&g_y[o0] = make_float2(v00, v01);
                *(float2*)&g_y[o1] = make_float2(v10, v11);
            }
        }
    }
}

// ---------------- combine ----------------
__global__ void combine_kernel(float* __restrict__ out) {
    int t = blockIdx.x;
    int a0 = g_assign[t * 2 + 0];
    int a1 = g_assign[t * 2 + 1];
    float w0 = g_wgt[a0];
    float w1 = g_wgt[a1];
    const float4* y0 = (const float4*)(g_y + (size_t)a0 * HD);
    const float4* y1 = (const float4*)(g_y + (size_t)a1 * HD);
    float4* o = (float4*)(out + (size_t)t * HD);
    for (int h = threadIdx.x; h < HD / 4; h += blockDim.x) {
        float4 v0 = y0[h], v1 = y1[h], r;
        r.x = w0 * v0.x + w1 * v1.x;
        r.y = w0 * v0.y + w1 * v1.y;
        r.z = w0 * v0.z + w1 * v1.z;
        r.w = w0 * v0.w + w1 * v1.w;
        o[h] = r;
    }
}

extern "C" void kernel_launch(void* const* d_in, const int* in_sizes, int n_in,
                              void* d_out, int out_size) {
    const float* x  = (const float*)d_in[0];
    const float* Wg = (const float*)d_in[1];
    const float* W1 = (const float*)d_in[2];
    const float* b1 = (const float*)d_in[3];
    const float* W2 = (const float*)d_in[4];
    const float* b2 = (const float*)d_in[5];
    float* out = (float*)d_out;

    static int init_done = 0;
    if (!init_done) {
        cudaFuncSetAttribute(moe_mma_kernel<HD, ID, true>,
                             cudaFuncAttributeMaxDynamicSharedMemorySize, SMEM_TOTAL);
        cudaFuncSetAttribute(moe_mma_kernel<ID, HD, false>,
                             cudaFuncAttributeMaxDynamicSharedMemorySize, SMEM_TOTAL);
        init_done = 1;
    }

    __half2 *w1, *w2;
    cudaGetSymbolAddress((void**)&w1, g_w1);
    cudaGetSymbolAddress((void**)&w2, g_w2);
    const __half *xp, *actp;
    cudaGetSymbolAddress((void**)&xp, g_x);
    cudaGetSymbolAddress((void**)&actp, g_act);

    reset_kernel<<<1, 32>>>();
    router_kernel<<<NT / 4, 128>>>(x, Wg);
    const size_t n4 = (size_t)NE * ID * HD / 4;
    wconv_kernel<<<4096, 256>>>((const float4*)W1, w1, n4);
    wconv_kernel<<<4096, 256>>>((const float4*)W2, w2, n4);
    gather_kernel<<<dim3(NT / BM, NE), 256>>>(x);

    moe_mma_kernel<HD, ID, true><<<dim3(NT / BM, ID / BN, NE), 256, SMEM_TOTAL>>>(
        xp, (const __half*)w1, b1);
    moe_mma_kernel<ID, HD, false><<<dim3(NT / BM, HD / BN, NE), 256, SMEM_TOTAL>>>(
        actp, (const __half*)w2, b2);

    combine_kernel<<<NT, 256>>>(out);
}